// round 5
// baseline (speedup 1.0000x reference)
#include <cuda_runtime.h>
#include <math.h>

#define DD 64
#define NMAX 100000
#define EMAX 1200000
#define EPS 1e-15f
#define CLIP (1.0f - 1e-7f)

// scratch (no allocs allowed -> __device__ globals)
__device__ float g_invdeg[NMAX];
__device__ float g_h[(size_t)NMAX * DD];
__device__ float g_neigh[(size_t)NMAX * DD];

// ---------------------------------------------------------------- utilities

__global__ void k_zero4(float4* p, int n4) {
    int i = blockIdx.x * blockDim.x + threadIdx.x;
    if (i < n4) p[i] = make_float4(0.f, 0.f, 0.f, 0.f);
}

__global__ void k_deg(const int* __restrict__ dst, int E, float* __restrict__ deg) {
    int i = blockIdx.x * blockDim.x + threadIdx.x;
    if (i < E) atomicAdd(&deg[dst[i]], 1.0f);
}

__global__ void k_invdeg(float* __restrict__ deg, int N) {
    int i = blockIdx.x * blockDim.x + threadIdx.x;
    if (i < N) {
        float d = deg[i];
        deg[i] = (d > 0.f) ? (1.0f / d) : 0.f;
    }
}

// ---------------------------------------------------------------- fused transform + GEMM
// MODE 0: tangent = logmap0(xin, c)
// MODE 1: tangent = xin * invdeg   (logmap0(expmap0(u)) == u shortcut)
// hout[n, j] = sum_k tangent[n,k] * W[j,k] + b[j]
template <int MODE>
__global__ void __launch_bounds__(256)
k_layer(const float* __restrict__ xin, const float* __restrict__ W,
        const float* __restrict__ b, const float* __restrict__ curv,
        const float* __restrict__ invdeg, float* __restrict__ hout, int N)
{
    __shared__ float Wsh[64 * 68];   // stride 68: conflict-free LDS.128 by row
    __shared__ float tS[64 * 64];    // 64 nodes x 64 dims (reads are broadcast)

    const int t = threadIdx.x;
    const float sc = sqrtf(fabsf(curv[0]));

    // stage W
    #pragma unroll 4
    for (int i = t; i < 4096; i += 256)
        Wsh[(i >> 6) * 68 + (i & 63)] = W[i];

    // phase 1: tangents for 64 nodes (4 threads/node, 16 dims each)
    {
        const int nl = t >> 2;          // local node 0..63
        const int q  = t & 3;           // quarter
        const int gn = blockIdx.x * 64 + nl;
        float vals[16];
        #pragma unroll
        for (int i = 0; i < 16; i++) vals[i] = 0.f;
        float ss = 0.f;
        if (gn < N) {
            const float4* xp = (const float4*)(xin + (size_t)gn * DD + q * 16);
            #pragma unroll
            for (int i = 0; i < 4; i++) {
                float4 v = xp[i];
                vals[4*i+0] = v.x; vals[4*i+1] = v.y;
                vals[4*i+2] = v.z; vals[4*i+3] = v.w;
                ss += v.x*v.x + v.y*v.y + v.z*v.z + v.w*v.w;
            }
        }
        float factor;
        if (MODE == 0) {
            ss += __shfl_xor_sync(0xffffffffu, ss, 1);
            ss += __shfl_xor_sync(0xffffffffu, ss, 2);
            float nm = fmaxf(sqrtf(ss), EPS);
            float a  = fminf(sc * nm, CLIP);
            factor = atanhf(a) / (sc * nm);
        } else {
            factor = (gn < N) ? invdeg[gn] : 0.f;
        }
        float* tp = &tS[nl * 64 + q * 16];
        #pragma unroll
        for (int i = 0; i < 16; i++) tp[i] = vals[i] * factor;
    }
    __syncthreads();

    // phase 2: each warp computes 8 nodes; lane j owns output rows j and j+32
    {
        const int w = t >> 5;
        const int j = t & 31;
        const float b0 = b[j];
        const float b1 = b[j + 32];
        float a0[8], a1[8];
        #pragma unroll
        for (int nn = 0; nn < 8; nn++) { a0[nn] = 0.f; a1[nn] = 0.f; }

        #pragma unroll 4
        for (int k = 0; k < 64; k += 4) {
            float4 w0 = *(const float4*)&Wsh[j * 68 + k];
            float4 w1 = *(const float4*)&Wsh[(j + 32) * 68 + k];
            #pragma unroll
            for (int nn = 0; nn < 8; nn++) {
                float4 tv = *(const float4*)&tS[(w * 8 + nn) * 64 + k];
                a0[nn] += w0.x*tv.x + w0.y*tv.y + w0.z*tv.z + w0.w*tv.w;
                a1[nn] += w1.x*tv.x + w1.y*tv.y + w1.z*tv.z + w1.w*tv.w;
            }
        }
        #pragma unroll
        for (int nn = 0; nn < 8; nn++) {
            int gn = blockIdx.x * 64 + w * 8 + nn;
            if (gn < N) {
                hout[(size_t)gn * DD + j]      = a0[nn] + b0;
                hout[(size_t)gn * DD + 32 + j] = a1[nn] + b1;
            }
        }
    }
}

// ---------------------------------------------------------------- edge scatter-add
// 16 threads per edge, 4 dims each, vector reductions into L2
__global__ void __launch_bounds__(256)
k_scatter(const int* __restrict__ src, const int* __restrict__ dst,
          const float* __restrict__ h, float* __restrict__ out, int E)
{
    int tid = blockIdx.x * blockDim.x + threadIdx.x;
    int e = tid >> 4;
    int part = tid & 15;
    if (e < E) {
        int s = __ldg(&src[e]);
        int d = __ldg(&dst[e]);
        float4 v = __ldg((const float4*)(h + (size_t)s * DD + part * 4));
        float4* p = (float4*)(out + (size_t)d * DD + part * 4);
#if __CUDA_ARCH__ >= 900
        atomicAdd(p, v);   // vector f32 reduction (RED.ADD.v4)
#else
        float* pf = (float*)p;
        atomicAdd(pf + 0, v.x); atomicAdd(pf + 1, v.y);
        atomicAdd(pf + 2, v.z); atomicAdd(pf + 3, v.w);
#endif
    }
}

// ---------------------------------------------------------------- final scale + expmap0
__global__ void __launch_bounds__(256)
k_expmap(const float* __restrict__ neigh, const float* __restrict__ invdeg,
         const float* __restrict__ curv, float* __restrict__ out, int N)
{
    int warp = (blockIdx.x * blockDim.x + threadIdx.x) >> 5;
    int lane = threadIdx.x & 31;
    if (warp >= N) return;
    const float sc = sqrtf(fabsf(curv[0]));
    float2 v = *(const float2*)(neigh + (size_t)warp * DD + lane * 2);
    float id = invdeg[warp];
    v.x *= id; v.y *= id;
    float ss = v.x * v.x + v.y * v.y;
    #pragma unroll
    for (int o = 16; o; o >>= 1) ss += __shfl_xor_sync(0xffffffffu, ss, o);
    float nm = fmaxf(sqrtf(ss), EPS);
    float f = tanhf(sc * nm) / (sc * nm);
    float2 o2 = make_float2(v.x * f, v.y * f);
    *(float2*)(out + (size_t)warp * DD + lane * 2) = o2;
}

// ---------------------------------------------------------------- launch
extern "C" void kernel_launch(void* const* d_in, const int* in_sizes, int n_in,
                              void* d_out, int out_size)
{
    const int*   src  = (const int*)d_in[0];
    const int*   dst  = (const int*)d_in[1];
    const float* emb  = (const float*)d_in[2];
    const float* W1   = (const float*)d_in[3];
    const float* b1   = (const float*)d_in[4];
    const float* W2   = (const float*)d_in[5];
    const float* b2   = (const float*)d_in[6];
    const float* curv = (const float*)d_in[7];
    float*       out  = (float*)d_out;

    const int E = in_sizes[0];
    const int N = in_sizes[2] / DD;

    float* invdeg = nullptr; float* h = nullptr; float* neigh = nullptr;
    cudaGetSymbolAddress((void**)&invdeg, g_invdeg);
    cudaGetSymbolAddress((void**)&h,      g_h);
    cudaGetSymbolAddress((void**)&neigh,  g_neigh);

    const int T = 256;
    const int nNodeBlk   = (N + 63) / 64;
    const int nInvBlk    = (N + T - 1) / T;
    const int nDegBlk    = (E + T - 1) / T;
    const int nZeroN4    = (N + 3) / 4;               // invdeg zero (float4 count)
    const int nZeroNB    = (nZeroN4 + T - 1) / T;
    const int nFeat4     = (N * DD) / 4;              // 64 % 4 == 0
    const int nZeroFB    = (nFeat4 + T - 1) / T;
    const long long sThreads = (long long)E * 16;
    const int nScBlk     = (int)((sThreads + T - 1) / T);
    const int nExBlk     = (N * 32 + T - 1) / T;

    // degree -> inverse degree
    k_zero4<<<nZeroNB, T>>>((float4*)invdeg, nZeroN4);
    k_deg<<<nDegBlk, T>>>(dst, E, invdeg);
    k_invdeg<<<nInvBlk, T>>>(invdeg, N);

    // layer 1: logmap(emb) @ W1^T + b1 -> h ; scatter -> neigh
    k_layer<0><<<nNodeBlk, T>>>(emb, W1, b1, curv, nullptr, h, N);
    k_zero4<<<nZeroFB, T>>>((float4*)neigh, nFeat4);
    k_scatter<<<nScBlk, T>>>(src, dst, h, neigh, E);

    // layer 2: (neigh * invdeg) @ W2^T + b2 -> h ; scatter -> neigh
    k_layer<1><<<nNodeBlk, T>>>(neigh, W2, b2, curv, invdeg, h, N);
    k_zero4<<<nZeroFB, T>>>((float4*)neigh, nFeat4);
    k_scatter<<<nScBlk, T>>>(src, dst, h, neigh, E);

    // final expmap0 of the mean
    k_expmap<<<nExBlk, T>>>(neigh, invdeg, curv, out, N);
}

// round 10
// speedup vs baseline: 1.2642x; 1.2642x over previous
#include <cuda_runtime.h>
#include <math.h>

#define DD 64
#define NMAX 100000
#define EMAX 1200000
#define EPS 1e-15f
#define CLIP (1.0f - 1e-7f)

// ---------------- scratch (__device__ globals; no allocs allowed) ----------
__device__ int   g_deg[NMAX];
__device__ int   g_cur[NMAX];
__device__ int   g_rowptr[NMAX + 1];
__device__ int   g_bsum[128];
__device__ int   g_esrc[EMAX];
__device__ float g_invdeg[NMAX];
__device__ float g_t[(size_t)NMAX * DD];     // tangent buffer (scatter source)
__device__ float g_agg[(size_t)NMAX * DD];   // aggregated (invdeg-scaled) buffer

// ---------------------------------------------------------------- CSR build

__global__ void k_init(int* __restrict__ deg, int* __restrict__ cur, int N) {
    int i = blockIdx.x * blockDim.x + threadIdx.x;
    if (i < N) { deg[i] = 0; cur[i] = 0; }
}

__global__ void k_count(const int* __restrict__ dst, int E, int* __restrict__ deg) {
    int i = blockIdx.x * blockDim.x + threadIdx.x;
    if (i < E) atomicAdd(&deg[dst[i]], 1);
}

// per-block exclusive scan (1024/block), block totals to bsum
__global__ void k_scan1(const int* __restrict__ deg, int* __restrict__ rowptr,
                        int* __restrict__ bsum, int N) {
    __shared__ int sh[1024];
    int t = threadIdx.x;
    int i = blockIdx.x * 1024 + t;
    int v = (i < N) ? deg[i] : 0;
    sh[t] = v;
    __syncthreads();
    #pragma unroll
    for (int o = 1; o < 1024; o <<= 1) {
        int x = (t >= o) ? sh[t - o] : 0;
        __syncthreads();
        sh[t] += x;
        __syncthreads();
    }
    if (i < N) rowptr[i] = sh[t] - v;           // exclusive
    if (t == 1023) bsum[blockIdx.x] = sh[1023]; // block total
}

// scan block totals (nb <= 128), in place exclusive
__global__ void k_scan2(int* __restrict__ bsum, int nb) {
    __shared__ int sh[128];
    int t = threadIdx.x;
    int v = (t < nb) ? bsum[t] : 0;
    sh[t] = v;
    __syncthreads();
    #pragma unroll
    for (int o = 1; o < 128; o <<= 1) {
        int x = (t >= o) ? sh[t - o] : 0;
        __syncthreads();
        sh[t] += x;
        __syncthreads();
    }
    if (t < nb) bsum[t] = sh[t] - v;
}

// add block offsets; also invdeg and rowptr[N]
__global__ void k_scan3(int* __restrict__ rowptr, const int* __restrict__ bsum,
                        const int* __restrict__ deg, float* __restrict__ invdeg,
                        int N, int E) {
    int i = blockIdx.x * blockDim.x + threadIdx.x;
    if (i < N) {
        rowptr[i] += bsum[i >> 10];
        int d = deg[i];
        invdeg[i] = (d > 0) ? (1.0f / (float)d) : 0.f;
    }
    if (i == 0) rowptr[N] = E;
}

__global__ void k_place(const int* __restrict__ src, const int* __restrict__ dst,
                        const int* __restrict__ rowptr, int* __restrict__ cur,
                        int* __restrict__ esrc, int E) {
    int e = blockIdx.x * blockDim.x + threadIdx.x;
    if (e < E) {
        int d = dst[e];
        int pos = rowptr[d] + atomicAdd(&cur[d], 1);
        esrc[pos] = src[e];
    }
}

// ---------------------------------------------------------------- logmap0 (warp/node)

__global__ void __launch_bounds__(256)
k_logmap(const float* __restrict__ x, const float* __restrict__ curv,
         float* __restrict__ t, int N) {
    int w = (blockIdx.x * blockDim.x + threadIdx.x) >> 5;
    int lane = threadIdx.x & 31;
    if (w >= N) return;
    const float sc = sqrtf(fabsf(curv[0]));
    float2 v = *(const float2*)(x + (size_t)w * DD + lane * 2);
    float ss = v.x * v.x + v.y * v.y;
    #pragma unroll
    for (int o = 16; o; o >>= 1) ss += __shfl_xor_sync(0xffffffffu, ss, o);
    float nm = fmaxf(sqrtf(ss), EPS);
    float a  = fminf(sc * nm, CLIP);
    float f  = atanhf(a) / (sc * nm);
    float2 o2 = make_float2(v.x * f, v.y * f);
    *(float2*)(t + (size_t)w * DD + lane * 2) = o2;
}

// ---------------------------------------------------------------- CSR aggregate
// one warp per dst node; lane owns dims [2l, 2l+1]; writes invdeg-scaled sum once
__global__ void __launch_bounds__(256)
k_agg(const int* __restrict__ rowptr, const int* __restrict__ esrc,
      const float* __restrict__ t, const float* __restrict__ invdeg,
      float* __restrict__ agg, int N) {
    int d = (blockIdx.x * blockDim.x + threadIdx.x) >> 5;
    int lane = threadIdx.x & 31;
    if (d >= N) return;
    int beg = rowptr[d], end = rowptr[d + 1];
    float ax = 0.f, ay = 0.f;
    int e = beg;
    for (; e + 4 <= end; e += 4) {
        int s0 = esrc[e], s1 = esrc[e + 1], s2 = esrc[e + 2], s3 = esrc[e + 3];
        float2 v0 = *(const float2*)(t + (size_t)s0 * DD + lane * 2);
        float2 v1 = *(const float2*)(t + (size_t)s1 * DD + lane * 2);
        float2 v2 = *(const float2*)(t + (size_t)s2 * DD + lane * 2);
        float2 v3 = *(const float2*)(t + (size_t)s3 * DD + lane * 2);
        ax += v0.x + v1.x + v2.x + v3.x;
        ay += v0.y + v1.y + v2.y + v3.y;
    }
    for (; e < end; e++) {
        int s = esrc[e];
        float2 v = *(const float2*)(t + (size_t)s * DD + lane * 2);
        ax += v.x; ay += v.y;
    }
    float id = invdeg[d];
    float2 o2 = make_float2(ax * id, ay * id);
    *(float2*)(agg + (size_t)d * DD + lane * 2) = o2;
}

// ---------------------------------------------------------------- GEMM (+ optional expmap)
// y[n,j] = agg[n,:] . W[j,:] + b[j]*mask(n);  EXP: out = expmap0(y), else write t
template <int EXP>
__global__ void __launch_bounds__(256)
k_gemm(const float* __restrict__ xin, const float* __restrict__ W,
       const float* __restrict__ b, const float* __restrict__ curv,
       const float* __restrict__ invdeg, float* __restrict__ yout, int N)
{
    __shared__ float Wsh[64 * 68];
    __shared__ float tS[64 * 64];
    __shared__ float mk[64];

    const int t = threadIdx.x;
    const float sc = sqrtf(fabsf(curv[0]));

    #pragma unroll 4
    for (int i = t; i < 4096; i += 256)
        Wsh[(i >> 6) * 68 + (i & 63)] = W[i];

    // stage input (already invdeg-scaled) + bias mask
    {
        const int nl = t >> 2;
        const int q  = t & 3;
        const int gn = blockIdx.x * 64 + nl;
        float4 vs[4];
        if (gn < N) {
            const float4* xp = (const float4*)(xin + (size_t)gn * DD + q * 16);
            #pragma unroll
            for (int i = 0; i < 4; i++) vs[i] = xp[i];
        } else {
            #pragma unroll
            for (int i = 0; i < 4; i++) vs[i] = make_float4(0.f, 0.f, 0.f, 0.f);
        }
        float4* tp = (float4*)&tS[nl * 64 + q * 16];
        #pragma unroll
        for (int i = 0; i < 4; i++) tp[i] = vs[i];
        if (q == 0) mk[nl] = (gn < N && invdeg[gn] > 0.f) ? 1.f : 0.f;
    }
    __syncthreads();

    // each warp: 8 nodes; lane j owns output dims j and j+32
    {
        const int w = t >> 5;
        const int j = t & 31;
        const float b0 = b[j];
        const float b1 = b[j + 32];
        float a0[8], a1[8];
        #pragma unroll
        for (int nn = 0; nn < 8; nn++) { a0[nn] = 0.f; a1[nn] = 0.f; }

        #pragma unroll 4
        for (int k = 0; k < 64; k += 4) {
            float4 w0 = *(const float4*)&Wsh[j * 68 + k];
            float4 w1 = *(const float4*)&Wsh[(j + 32) * 68 + k];
            #pragma unroll
            for (int nn = 0; nn < 8; nn++) {
                float4 tv = *(const float4*)&tS[(w * 8 + nn) * 64 + k];
                a0[nn] += w0.x*tv.x + w0.y*tv.y + w0.z*tv.z + w0.w*tv.w;
                a1[nn] += w1.x*tv.x + w1.y*tv.y + w1.z*tv.z + w1.w*tv.w;
            }
        }

        #pragma unroll
        for (int nn = 0; nn < 8; nn++) {
            int gn = blockIdx.x * 64 + w * 8 + nn;
            if (gn >= N) continue;
            float m = mk[w * 8 + nn];
            float v0 = a0[nn] + b0 * m;
            float v1 = a1[nn] + b1 * m;
            if (EXP) {
                float ss = v0 * v0 + v1 * v1;
                #pragma unroll
                for (int o = 16; o; o >>= 1) ss += __shfl_xor_sync(0xffffffffu, ss, o);
                float nm = fmaxf(sqrtf(ss), EPS);
                float f  = tanhf(sc * nm) / (sc * nm);
                v0 *= f; v1 *= f;
            }
            yout[(size_t)gn * DD + j]      = v0;
            yout[(size_t)gn * DD + 32 + j] = v1;
        }
    }
}

// ---------------------------------------------------------------- launch

extern "C" void kernel_launch(void* const* d_in, const int* in_sizes, int n_in,
                              void* d_out, int out_size)
{
    const int*   src  = (const int*)d_in[0];
    const int*   dst  = (const int*)d_in[1];
    const float* emb  = (const float*)d_in[2];
    const float* W1   = (const float*)d_in[3];
    const float* b1   = (const float*)d_in[4];
    const float* W2   = (const float*)d_in[5];
    const float* b2   = (const float*)d_in[6];
    const float* curv = (const float*)d_in[7];
    float*       out  = (float*)d_out;

    const int E = in_sizes[0];
    const int N = in_sizes[2] / DD;

    int *deg, *cur, *rowptr, *bsum, *esrc;
    float *invdeg, *t, *agg;
    cudaGetSymbolAddress((void**)&deg,    g_deg);
    cudaGetSymbolAddress((void**)&cur,    g_cur);
    cudaGetSymbolAddress((void**)&rowptr, g_rowptr);
    cudaGetSymbolAddress((void**)&bsum,   g_bsum);
    cudaGetSymbolAddress((void**)&esrc,   g_esrc);
    cudaGetSymbolAddress((void**)&invdeg, g_invdeg);
    cudaGetSymbolAddress((void**)&t,      g_t);
    cudaGetSymbolAddress((void**)&agg,    g_agg);

    const int T = 256;
    const int nb      = (N + 1023) / 1024;       // scan blocks (<=128)
    const int nNB     = (N + T - 1) / T;
    const int nEB     = (E + T - 1) / T;
    const int nWarpB  = ((N * 32) + T - 1) / T;  // warp-per-node kernels
    const int nGemmB  = (N + 63) / 64;

    // CSR by dst: count -> scan -> place (also invdeg)
    k_init <<<nNB, T>>>(deg, cur, N);
    k_count<<<nEB, T>>>(dst, E, deg);
    k_scan1<<<nb, 1024>>>(deg, rowptr, bsum, N);
    k_scan2<<<1, 128>>>(bsum, nb);
    k_scan3<<<nNB, T>>>(rowptr, bsum, deg, invdeg, N, E);
    k_place<<<nEB, T>>>(src, dst, rowptr, cur, esrc, E);

    // layer 1: t = logmap(emb); agg = invdeg * sum_src t; t = agg@W1^T + b1*mask
    k_logmap<<<nWarpB, T>>>(emb, curv, t, N);
    k_agg   <<<nWarpB, T>>>(rowptr, esrc, t, invdeg, agg, N);
    k_gemm<0><<<nGemmB, T>>>(agg, W1, b1, curv, invdeg, t, N);

    // layer 2: agg = invdeg * sum_src t; out = expmap(agg@W2^T + b2*mask)
    k_agg   <<<nWarpB, T>>>(rowptr, esrc, t, invdeg, agg, N);
    k_gemm<1><<<nGemmB, T>>>(agg, W2, b2, curv, invdeg, out, N);
}

// round 13
// speedup vs baseline: 1.2808x; 1.0132x over previous
#include <cuda_runtime.h>
#include <cuda_fp16.h>
#include <math.h>

#define DD 64
#define NMAX 100000
#define EMAX 1200000
#define EPS 1e-15f
#define CLIP (1.0f - 1e-7f)

// ---------------- scratch (__device__ globals; no allocs allowed) ----------
__device__ int    g_ints[2 * NMAX + 1];        // [0,N): deg  [N,2N): cur  [2N]: counter
__device__ int    g_rowptr[NMAX];              // segment begin per dst node
__device__ int    g_esrc[EMAX];                // src ids grouped by dst
__device__ float  g_invdeg[NMAX];
__device__ __half g_t[(size_t)NMAX * DD];      // fp16 tangent buffer (gather source)
__device__ float  g_agg[(size_t)NMAX * DD];    // aggregated (invdeg-scaled), fp32

// ---------------------------------------------------------------- CSR build

__global__ void k_count(const int* __restrict__ dst, int E, int* __restrict__ deg) {
    int i = blockIdx.x * blockDim.x + threadIdx.x;
    if (i < E) atomicAdd(&deg[dst[i]], 1);
}

// one pass: warp-aggregated atomic segment offsets + invdeg
__global__ void k_offsets(const int* __restrict__ deg, int* __restrict__ rowptr,
                          float* __restrict__ invdeg, int* __restrict__ counter, int N) {
    int i = blockIdx.x * blockDim.x + threadIdx.x;
    int lane = threadIdx.x & 31;
    int d = (i < N) ? deg[i] : 0;
    // inclusive warp scan of d
    int pre = d;
    #pragma unroll
    for (int o = 1; o < 32; o <<= 1) {
        int x = __shfl_up_sync(0xffffffffu, pre, o);
        if (lane >= o) pre += x;
    }
    int total = __shfl_sync(0xffffffffu, pre, 31);
    int base = 0;
    if (lane == 0) base = atomicAdd(counter, total);
    base = __shfl_sync(0xffffffffu, base, 0);
    if (i < N) {
        rowptr[i] = base + (pre - d);
        invdeg[i] = (d > 0) ? (1.0f / (float)d) : 0.f;
    }
}

__global__ void k_place(const int* __restrict__ src, const int* __restrict__ dst,
                        const int* __restrict__ rowptr, int* __restrict__ cur,
                        int* __restrict__ esrc, int E) {
    int e = blockIdx.x * blockDim.x + threadIdx.x;
    if (e < E) {
        int d = dst[e];
        int pos = rowptr[d] + atomicAdd(&cur[d], 1);
        esrc[pos] = src[e];
    }
}

// ---------------------------------------------------------------- logmap0 -> fp16

__global__ void __launch_bounds__(256)
k_logmap(const float* __restrict__ x, const float* __restrict__ curv,
         __half* __restrict__ t, int N) {
    int w = (blockIdx.x * blockDim.x + threadIdx.x) >> 5;
    int lane = threadIdx.x & 31;
    if (w >= N) return;
    const float sc = sqrtf(fabsf(curv[0]));
    float2 v = *(const float2*)(x + (size_t)w * DD + lane * 2);
    float ss = v.x * v.x + v.y * v.y;
    #pragma unroll
    for (int o = 16; o; o >>= 1) ss += __shfl_xor_sync(0xffffffffu, ss, o);
    float nm = fmaxf(sqrtf(ss), EPS);
    float a  = fminf(sc * nm, CLIP);
    float f  = atanhf(a) / (sc * nm);
    ((__half2*)t)[(size_t)w * 32 + lane] =
        __float22half2_rn(make_float2(v.x * f, v.y * f));
}

// ---------------------------------------------------------------- CSR aggregate
// one warp per dst node; lane owns dims [2l,2l+1] (one half2 per edge); fp32 accum
__global__ void __launch_bounds__(256)
k_agg(const int* __restrict__ rowptr, const int* __restrict__ deg,
      const int* __restrict__ esrc, const __half* __restrict__ t,
      const float* __restrict__ invdeg, float* __restrict__ agg, int N) {
    int d = (blockIdx.x * blockDim.x + threadIdx.x) >> 5;
    int lane = threadIdx.x & 31;
    if (d >= N) return;
    int beg = rowptr[d];
    int end = beg + deg[d];
    const __half2* tp = (const __half2*)t;
    float ax = 0.f, ay = 0.f;
    int e = beg;
    for (; e + 8 <= end; e += 8) {
        int s[8];
        #pragma unroll
        for (int i = 0; i < 8; i++) s[i] = esrc[e + i];
        #pragma unroll
        for (int i = 0; i < 8; i++) {
            float2 f = __half22float2(tp[(size_t)s[i] * 32 + lane]);
            ax += f.x; ay += f.y;
        }
    }
    for (; e < end; e++) {
        float2 f = __half22float2(tp[(size_t)esrc[e] * 32 + lane]);
        ax += f.x; ay += f.y;
    }
    float id = invdeg[d];
    *(float2*)(agg + (size_t)d * DD + lane * 2) = make_float2(ax * id, ay * id);
}

// ---------------------------------------------------------------- GEMM
// MODE 0: yhalf = agg@W^T + b*mask            (fp16 out, smem-staged coalesced)
// MODE 1: yfloat = expmap0(agg@W^T + b*mask)  (fp32 out)
template <int MODE>
__global__ void __launch_bounds__(256)
k_gemm(const float* __restrict__ xin, const float* __restrict__ W,
       const float* __restrict__ b, const float* __restrict__ curv,
       const float* __restrict__ invdeg, float* __restrict__ yfloat,
       __half* __restrict__ yhalf, int N)
{
    __shared__ float Wsh[64 * 68];
    __shared__ float tS[64 * 64];     // reused as fp16 staging after compute
    __shared__ float mk[64];

    const int t = threadIdx.x;
    const float sc = sqrtf(fabsf(curv[0]));

    #pragma unroll 4
    for (int i = t; i < 4096; i += 256)
        Wsh[(i >> 6) * 68 + (i & 63)] = W[i];

    // stage input + bias mask
    {
        const int nl = t >> 2;
        const int q  = t & 3;
        const int gn = blockIdx.x * 64 + nl;
        float4 vs[4];
        if (gn < N) {
            const float4* xp = (const float4*)(xin + (size_t)gn * DD + q * 16);
            #pragma unroll
            for (int i = 0; i < 4; i++) vs[i] = xp[i];
        } else {
            #pragma unroll
            for (int i = 0; i < 4; i++) vs[i] = make_float4(0.f, 0.f, 0.f, 0.f);
        }
        float4* tp = (float4*)&tS[nl * 64 + q * 16];
        #pragma unroll
        for (int i = 0; i < 4; i++) tp[i] = vs[i];
        if (q == 0) mk[nl] = (gn < N && invdeg[gn] > 0.f) ? 1.f : 0.f;
    }
    __syncthreads();

    const int w = t >> 5;
    const int j = t & 31;
    const float b0 = b[j];
    const float b1 = b[j + 32];
    float a0[8], a1[8];
    #pragma unroll
    for (int nn = 0; nn < 8; nn++) { a0[nn] = 0.f; a1[nn] = 0.f; }

    #pragma unroll 4
    for (int k = 0; k < 64; k += 4) {
        float4 w0 = *(const float4*)&Wsh[j * 68 + k];
        float4 w1 = *(const float4*)&Wsh[(j + 32) * 68 + k];
        #pragma unroll
        for (int nn = 0; nn < 8; nn++) {
            float4 tv = *(const float4*)&tS[(w * 8 + nn) * 64 + k];
            a0[nn] += w0.x*tv.x + w0.y*tv.y + w0.z*tv.z + w0.w*tv.w;
            a1[nn] += w1.x*tv.x + w1.y*tv.y + w1.z*tv.z + w1.w*tv.w;
        }
    }

    if (MODE == 1) {
        #pragma unroll
        for (int nn = 0; nn < 8; nn++) {
            int gn = blockIdx.x * 64 + w * 8 + nn;
            if (gn >= N) continue;
            float m = mk[w * 8 + nn];
            float v0 = a0[nn] + b0 * m;
            float v1 = a1[nn] + b1 * m;
            float ss = v0 * v0 + v1 * v1;
            #pragma unroll
            for (int o = 16; o; o >>= 1) ss += __shfl_xor_sync(0xffffffffu, ss, o);
            float nm = fmaxf(sqrtf(ss), EPS);
            float f  = tanhf(sc * nm) / (sc * nm);
            yfloat[(size_t)gn * DD + j]      = v0 * f;
            yfloat[(size_t)gn * DD + 32 + j] = v1 * f;
        }
    } else {
        // all warps done reading tS before aliasing it as fp16 staging
        __syncthreads();
        __half* hS = (__half*)tS;
        #pragma unroll
        for (int nn = 0; nn < 8; nn++) {
            float m = mk[w * 8 + nn];
            hS[(w * 8 + nn) * 64 + j]      = __float2half(a0[nn] + b0 * m);
            hS[(w * 8 + nn) * 64 + 32 + j] = __float2half(a1[nn] + b1 * m);
        }
        __syncthreads();
        // coalesced 16B writes: 4 threads per node, 2 x uint4 each
        const int nl = t >> 2;
        const int q  = t & 3;
        const int gn = blockIdx.x * 64 + nl;
        if (gn < N) {
            const uint4* srcp = (const uint4*)(hS + nl * 64);
            uint4* dstp = (uint4*)(yhalf + (size_t)gn * DD);
            dstp[q * 2]     = srcp[q * 2];
            dstp[q * 2 + 1] = srcp[q * 2 + 1];
        }
    }
}

// ---------------------------------------------------------------- launch

extern "C" void kernel_launch(void* const* d_in, const int* in_sizes, int n_in,
                              void* d_out, int out_size)
{
    const int*   src  = (const int*)d_in[0];
    const int*   dst  = (const int*)d_in[1];
    const float* emb  = (const float*)d_in[2];
    const float* W1   = (const float*)d_in[3];
    const float* b1   = (const float*)d_in[4];
    const float* W2   = (const float*)d_in[5];
    const float* b2   = (const float*)d_in[6];
    const float* curv = (const float*)d_in[7];
    float*       out  = (float*)d_out;

    const int E = in_sizes[0];
    const int N = in_sizes[2] / DD;

    int *ints, *rowptr, *esrc;
    float *invdeg, *agg;
    __half* t;
    cudaGetSymbolAddress((void**)&ints,   g_ints);
    cudaGetSymbolAddress((void**)&rowptr, g_rowptr);
    cudaGetSymbolAddress((void**)&esrc,   g_esrc);
    cudaGetSymbolAddress((void**)&invdeg, g_invdeg);
    cudaGetSymbolAddress((void**)&t,      g_t);
    cudaGetSymbolAddress((void**)&agg,    g_agg);

    int* deg     = ints;
    int* cur     = ints + N;
    int* counter = ints + 2 * N;

    const int T = 256;
    const int nNB    = (N + T - 1) / T;
    const int nEB    = (E + T - 1) / T;
    const int nWarpB = ((N * 32) + T - 1) / T;
    const int nGemmB = (N + 63) / 64;

    // CSR by dst: zero -> count -> offsets(+invdeg) -> place
    cudaMemsetAsync(ints, 0, (size_t)(2 * N + 1) * sizeof(int));
    k_count  <<<nEB, T>>>(dst, E, deg);
    k_offsets<<<nNB, T>>>(deg, rowptr, invdeg, counter, N);
    k_place  <<<nEB, T>>>(src, dst, rowptr, cur, esrc, E);

    // layer 1: t = logmap(emb) [fp16]; agg = invdeg*sum t; t = agg@W1^T + b1*mask [fp16]
    k_logmap<<<nWarpB, T>>>(emb, curv, t, N);
    k_agg   <<<nWarpB, T>>>(rowptr, deg, esrc, t, invdeg, agg, N);
    k_gemm<0><<<nGemmB, T>>>(agg, W1, b1, curv, invdeg, nullptr, t, N);

    // layer 2: agg = invdeg*sum t; out = expmap(agg@W2^T + b2*mask) [fp32]
    k_agg   <<<nWarpB, T>>>(rowptr, deg, esrc, t, invdeg, agg, N);
    k_gemm<1><<<nGemmB, T>>>(agg, W2, b2, curv, invdeg, out, nullptr, N);
}